// round 1
// baseline (speedup 1.0000x reference)
#include <cuda_runtime.h>
#include <math.h>

// Problem constants (shapes are fixed by the dataset)
#define D      272      // capsule feature dim
#define NC     19       // num classes
#define NCPAD  20       // padded classes (even, for f32x2 pairs)
#define KCH    16       // k-chunk staged per iteration (272 = 17 * 16)
#define TROWS  256      // rows per block tile
#define CAPS_PAD 260    // padded row length of k-major caps tile (16B-aligned stride, conflict-friendly)
#define MAXROWS 65536
#define MAXNI   4096

typedef unsigned long long u64;

// Scratch (no allocations allowed in kernel_launch)
__device__ float g_proj[(size_t)MAXROWS * NCPAD];   // ~5.24 MB, L2-resident in pass 2
__device__ int   g_bound[MAXNI + 1];

// ---- packed f32x2 helpers (ptxas never auto-fuses; PTX-only path) ----
__device__ __forceinline__ u64 pack2(float lo, float hi) {
    u64 r; asm("mov.b64 %0, {%1, %2};" : "=l"(r) : "f"(lo), "f"(hi)); return r;
}
__device__ __forceinline__ u64 fma2(u64 a, u64 b, u64 c) {
    u64 r; asm("fma.rn.f32x2 %0, %1, %2, %3;" : "=l"(r) : "l"(a), "l"(b), "l"(c)); return r;
}
__device__ __forceinline__ float2 unpack2(u64 v) {
    float2 f; asm("mov.b64 {%0, %1}, %2;" : "=f"(f.x), "=f"(f.y) : "l"(v)); return f;
}

// ============================================================
// Pass 1: proj[row][c] = sum_k caps[row][k] * W[k][c]   (c < 20, col 19 zero-padded)
// Block: 128 threads, tile 256 rows x 20 cols.
// Thread: cg = tid&1 -> cols cg*10..cg*10+9 ; rg = tid>>1 -> rows rg*4..rg*4+3
// Accumulators: 4 rows x 5 col-pairs as f32x2.
// ============================================================
__global__ void __launch_bounds__(128) proj_kernel(const float* __restrict__ caps,
                                                   const float* __restrict__ Wm) {
    __shared__ __align__(16) float s_W[D * NCPAD];          // 21760 B
    __shared__ __align__(16) float s_caps[KCH][CAPS_PAD];   // 16640 B  (k-major tile)

    const int tid = threadIdx.x;
    const int rowbase = blockIdx.x * TROWS;

    // Stage W once, zero-fill padded column 19
    for (int i = tid; i < D * NCPAD; i += 128) {
        int k = i / NCPAD;
        int c = i - k * NCPAD;
        s_W[i] = (c < NC) ? Wm[k * NC + c] : 0.0f;
    }

    const int cg = tid & 1;
    const int rg = tid >> 1;          // 0..63

    u64 acc[4][5];
#pragma unroll
    for (int r = 0; r < 4; ++r)
#pragma unroll
        for (int u = 0; u < 5; ++u) acc[r][u] = 0ull;

#pragma unroll 1
    for (int kc = 0; kc < D / KCH; ++kc) {
        const int k0 = kc * KCH;
        __syncthreads();   // also orders s_W staging before first compute
        // Stage 256 rows x 16 k (1024 float4, 8 per thread), transposed to k-major
#pragma unroll
        for (int it = 0; it < 8; ++it) {
            int q  = tid + it * 128;
            int r  = q >> 2;
            int c4 = q & 3;
            float4 v = *(const float4*)&caps[(size_t)(rowbase + r) * D + k0 + c4 * 4];
            int kk = c4 * 4;
            s_caps[kk + 0][r] = v.x;
            s_caps[kk + 1][r] = v.y;
            s_caps[kk + 2][r] = v.z;
            s_caps[kk + 3][r] = v.w;
        }
        __syncthreads();

#pragma unroll
        for (int kk = 0; kk < KCH; ++kk) {
            const u64* wp = (const u64*)&s_W[(k0 + kk) * NCPAD + cg * 10];
            u64 w[5];
#pragma unroll
            for (int u = 0; u < 5; ++u) w[u] = wp[u];   // native LDS.64 col-pairs
            float4 a = *(const float4*)&s_caps[kk][rg * 4];
            u64 ar[4] = { pack2(a.x, a.x), pack2(a.y, a.y),
                          pack2(a.z, a.z), pack2(a.w, a.w) };
#pragma unroll
            for (int r = 0; r < 4; ++r)
#pragma unroll
                for (int u = 0; u < 5; ++u)
                    acc[r][u] = fma2(ar[r], w[u], acc[r][u]);
        }
    }

    // Write proj (row stride 20 floats, col-pair stores are 8B aligned)
#pragma unroll
    for (int r = 0; r < 4; ++r) {
        int row = rowbase + rg * 4 + r;
        float* op = &g_proj[(size_t)row * NCPAD + cg * 10];
#pragma unroll
        for (int u = 0; u < 5; ++u) {
            float2 f = unpack2(acc[r][u]);
            op[2 * u + 0] = f.x;
            op[2 * u + 1] = f.y;
        }
    }
}

// ============================================================
// Segment boundaries from sorted segment_ids.
// g_bound[s] = first p with seg[p] >= s ; g_bound[NI] = P. Handles empty segments.
// ============================================================
__global__ void bounds_kernel(const int* __restrict__ seg, int P, int NI) {
    int p = blockIdx.x * blockDim.x + threadIdx.x;
    if (p >= P) return;
    int cur  = seg[p];
    int prev = (p == 0) ? -1 : seg[p - 1];
    for (int s = prev + 1; s <= cur; ++s) g_bound[s] = p;
    if (p == P - 1) {
        for (int s = cur + 1; s <= NI; ++s) g_bound[s] = P;
    }
}

// ============================================================
// Pass 2: one warp per segment. Lanes 0..19 own channels; gather proj rows,
// mean, add bias, sigmoid.
// ============================================================
__global__ void __launch_bounds__(256) pool_kernel(const int* __restrict__ point_idx,
                                                   const float* __restrict__ bias,
                                                   float* __restrict__ out, int NI) {
    int warp = (blockIdx.x * blockDim.x + threadIdx.x) >> 5;
    int lane = threadIdx.x & 31;
    if (warp >= NI) return;

    int start = g_bound[warp];
    int end   = g_bound[warp + 1];

    float a0 = 0.f, a1 = 0.f, a2 = 0.f, a3 = 0.f;
    if (lane < NCPAD) {
        const int c = lane;
        int p = start;
        for (; p + 4 <= end; p += 4) {
            int i0 = point_idx[p + 0];
            int i1 = point_idx[p + 1];
            int i2 = point_idx[p + 2];
            int i3 = point_idx[p + 3];
            a0 += g_proj[(size_t)i0 * NCPAD + c];
            a1 += g_proj[(size_t)i1 * NCPAD + c];
            a2 += g_proj[(size_t)i2 * NCPAD + c];
            a3 += g_proj[(size_t)i3 * NCPAD + c];
        }
        for (; p < end; ++p) a0 += g_proj[(size_t)point_idx[p] * NCPAD + c];
    }

    if (lane < NC) {
        float acc = (a0 + a1) + (a2 + a3);
        int cnt = end - start;
        float denom = (float)(cnt > 0 ? cnt : 1);
        float x = acc / denom + bias[lane];
        out[(size_t)warp * NC + lane] = 1.0f / (1.0f + expf(-x));
    }
}

// ============================================================
extern "C" void kernel_launch(void* const* d_in, const int* in_sizes, int n_in,
                              void* d_out, int out_size) {
    const float* caps = (const float*)d_in[0];   // [65536, 272]
    const float* Wm   = (const float*)d_in[1];   // [272, 19]
    const float* bias = (const float*)d_in[2];   // [19]
    const int*   pidx = (const int*)d_in[3];     // [P]
    const int*   seg  = (const int*)d_in[4];     // [P] sorted

    const int P     = in_sizes[3];
    const int NI    = out_size / NC;             // 4096
    const int nrows = in_sizes[0] / D;           // 65536

    proj_kernel<<<nrows / TROWS, 128>>>(caps, Wm);
    bounds_kernel<<<(P + 255) / 256, 256>>>(seg, P, NI);
    pool_kernel<<<(NI * 32 + 255) / 256, 256>>>(pidx, bias, (float*)d_out, NI);
}